// round 2
// baseline (speedup 1.0000x reference)
#include <cuda_runtime.h>
#include <math.h>

// Problem constants
#define N_  50000
#define E_  800000
#define H_  64
#define FE_ 32
#define NT_ 3
#define ET_ 4
#define ETE_ 4
#define NEG_ 0.2f

// ---------------- device scratch (static, allowed) ----------------
__device__ __align__(16) float g_e0[E_ * H_];     // edge feature ping
__device__ __align__(16) float g_e1[E_ * H_];     // edge feature pong
__device__ __align__(16) float g_mj[N_ * H_];     // h @ WlinJ per node
__device__ __align__(16) float g_outA[N_ * H_];   // conv output ping
__device__ __align__(16) float g_outB[N_ * H_];   // conv output pong
__device__ float g_sI[N_];
__device__ float g_sJ[N_];
__device__ float g_sum[N_];
__device__ int   g_m[N_];
__device__ float g_logit[E_];
// fused per-layer weights
__device__ __align__(16) float g_W2[NT_ * H_ * H_];
__device__ __align__(16) float g_b2[NT_ * H_];
__device__ float g_wI[NT_ * H_];
__device__ float g_wJ[NT_ * H_];
__device__ float g_cI[NT_];
__device__ float g_cJ[NT_];
__device__ float g_eteWt[ET_];

// ---------------- helpers ----------------
__device__ __forceinline__ float lrelu(float x) { return x > 0.f ? x : NEG_ * x; }
__device__ __forceinline__ int   fenc(float f) { int i = __float_as_int(f); return i >= 0 ? i : i ^ 0x7FFFFFFF; }
__device__ __forceinline__ float fdec(int i)   { return __int_as_float(i >= 0 ? i : i ^ 0x7FFFFFFF); }

// ---------------- prep: fuse hetero weights ----------------
// grid = NT_*64 blocks of 64 threads.  block -> (t, k), thread -> o
__global__ void prep_kernel(const float* __restrict__ Whl,
                            const float* __restrict__ bhl,
                            const float* __restrict__ Ete,
                            const float* __restrict__ Watt,
                            const float* __restrict__ Wlin) {
    int b = blockIdx.x;
    int t = b >> 6;
    int k = b & 63;
    int o = threadIdx.x;
    const float* wrow = Whl + (t * 64 + k) * 64;

    float acc = 0.f;
    for (int m = 0; m < 64; m++) acc += wrow[m] * Wlin[m * 64 + o];
    g_W2[(t * 64 + k) * 64 + o] = acc;

    if (o == 0) { float a = 0.f; for (int m = 0; m < 64; m++) a += wrow[m] * Watt[m];      g_wI[t * 64 + k] = a; }
    if (o == 1) { float a = 0.f; for (int m = 0; m < 64; m++) a += wrow[m] * Watt[64 + m]; g_wJ[t * 64 + k] = a; }

    if (k == 0) {
        float a = 0.f;
        for (int m = 0; m < 64; m++) a += bhl[t * 64 + m] * Wlin[m * 64 + o];
        g_b2[t * 64 + o] = a;
        if (o == 2) { float c = 0.f; for (int m = 0; m < 64; m++) c += bhl[t * 64 + m] * Watt[m];      g_cI[t] = c; }
        if (o == 3) { float c = 0.f; for (int m = 0; m < 64; m++) c += bhl[t * 64 + m] * Watt[64 + m]; g_cJ[t] = c; }
    }
    if (b == 0 && o < ET_) {
        float a = 0.f;
        for (int j = 0; j < ETE_; j++) a += lrelu(Ete[o * ETE_ + j]) * Watt[128 + j];
        g_eteWt[o] = a;
    }
}

// ---------------- per-layer init ----------------
__global__ void init_kernel(float* __restrict__ out) {
    int i = blockIdx.x * blockDim.x + threadIdx.x;
    if (i < N_ * H_) out[i] = 0.f;
    if (i < N_) { g_m[i] = fenc(-INFINITY); g_sum[i] = 0.f; }
}

// ---------------- node pass: mj = act(x)@W2[t]+b2[t], sI, sJ ----------------
template <bool RELU>
__global__ void __launch_bounds__(128)
node_kernel(const float* __restrict__ xin, const int* __restrict__ ntype) {
    int n = blockIdx.x * blockDim.x + threadIdx.x;
    if (n >= N_) return;
    int t = ntype[n];

    const float4* W4 = reinterpret_cast<const float4*>(g_W2) + t * 1024;
    const float4* b4 = reinterpret_cast<const float4*>(g_b2) + t * 16;
    const float*  wi = g_wI + t * 64;
    const float*  wj = g_wJ + t * 64;

    float4 acc[16];
#pragma unroll
    for (int o4 = 0; o4 < 16; o4++) acc[o4] = b4[o4];
    float sI = g_cI[t], sJ = g_cJ[t];

    const float4* x4 = reinterpret_cast<const float4*>(xin) + n * 16;
#pragma unroll 1
    for (int kc = 0; kc < 16; kc++) {
        float4 v4 = x4[kc];
        if (RELU) {
            v4.x = fmaxf(v4.x, 0.f); v4.y = fmaxf(v4.y, 0.f);
            v4.z = fmaxf(v4.z, 0.f); v4.w = fmaxf(v4.w, 0.f);
        }
        float vv[4] = {v4.x, v4.y, v4.z, v4.w};
#pragma unroll
        for (int j = 0; j < 4; j++) {
            int k = kc * 4 + j;
            float v = vv[j];
            sI += v * wi[k];
            sJ += v * wj[k];
            const float4* wr = W4 + k * 16;
#pragma unroll
            for (int o4 = 0; o4 < 16; o4++) {
                float4 w = wr[o4];
                acc[o4].x += v * w.x; acc[o4].y += v * w.y;
                acc[o4].z += v * w.z; acc[o4].w += v * w.w;
            }
        }
    }
    float4* mj4 = reinterpret_cast<float4*>(g_mj) + n * 16;
#pragma unroll
    for (int o4 = 0; o4 < 16; o4++) mj4[o4] = acc[o4];
    g_sI[n] = sI;
    g_sJ[n] = sJ;
}

// ---------------- edge pass A: ea, logit, segment-max (+optional edge head) ----------------
template <int IN, bool RELU, bool EHEAD>
__global__ void __launch_bounds__(128)
edge_ea_kernel(const float* __restrict__ ein, const int* __restrict__ ei,
               const int* __restrict__ etype, const float* __restrict__ Wea,
               const float* __restrict__ Watt, float* __restrict__ eaout,
               const float* __restrict__ Wec, const float* __restrict__ bec,
               float* __restrict__ eout) {
    __shared__ float4 sW[IN * 16];
    __shared__ float  sWe[64];
    __shared__ float  sWec[ET_ * 64];
    __shared__ float  sBec[ET_];
    for (int i = threadIdx.x; i < IN * 16; i += blockDim.x)
        sW[i] = reinterpret_cast<const float4*>(Wea)[i];
    if (threadIdx.x < 64) sWe[threadIdx.x] = Watt[132 + threadIdx.x];
    if (EHEAD) {
        for (int i = threadIdx.x; i < ET_ * 64; i += blockDim.x) sWec[i] = Wec[i];
        if (threadIdx.x < ET_) sBec[threadIdx.x] = bec[threadIdx.x];
    }
    __syncthreads();

    int e = blockIdx.x * blockDim.x + threadIdx.x;
    if (e >= E_) return;

    float4 acc[16];
#pragma unroll
    for (int o4 = 0; o4 < 16; o4++) acc[o4] = make_float4(0.f, 0.f, 0.f, 0.f);

    const float4* in4 = reinterpret_cast<const float4*>(ein) + e * (IN / 4);
#pragma unroll 1
    for (int kc = 0; kc < IN / 4; kc++) {
        float4 v4 = in4[kc];
        if (RELU) {
            v4.x = fmaxf(v4.x, 0.f); v4.y = fmaxf(v4.y, 0.f);
            v4.z = fmaxf(v4.z, 0.f); v4.w = fmaxf(v4.w, 0.f);
        }
        float vv[4] = {v4.x, v4.y, v4.z, v4.w};
#pragma unroll
        for (int j = 0; j < 4; j++) {
            float v = vv[j];
            const float4* wr = sW + (kc * 4 + j) * 16;
#pragma unroll
            for (int o4 = 0; o4 < 16; o4++) {
                float4 w = wr[o4];
                acc[o4].x += v * w.x; acc[o4].y += v * w.y;
                acc[o4].z += v * w.z; acc[o4].w += v * w.w;
            }
        }
    }

    int t = etype[e];
    float pre = 0.f;
    float eo = 0.f;
    const float* wec = EHEAD ? (sWec + t * 64) : nullptr;
    float4* out4 = reinterpret_cast<float4*>(eaout) + e * 16;
#pragma unroll
    for (int o4 = 0; o4 < 16; o4++) {
        float4 a = acc[o4];
        a.x = lrelu(a.x); a.y = lrelu(a.y); a.z = lrelu(a.z); a.w = lrelu(a.w);
        pre += a.x * sWe[o4 * 4] + a.y * sWe[o4 * 4 + 1] +
               a.z * sWe[o4 * 4 + 2] + a.w * sWe[o4 * 4 + 3];
        if (EHEAD) {
            eo += fmaxf(a.x, 0.f) * wec[o4 * 4]     + fmaxf(a.y, 0.f) * wec[o4 * 4 + 1] +
                  fmaxf(a.z, 0.f) * wec[o4 * 4 + 2] + fmaxf(a.w, 0.f) * wec[o4 * 4 + 3];
        }
        out4[o4] = a;
    }
    if (EHEAD) eout[e] = eo + sBec[t];

    int src = ei[e];
    int dst = ei[E_ + e];
    float lg = lrelu(g_sI[dst] + g_sJ[src] + pre + g_eteWt[t]);
    g_logit[e] = lg;
    atomicMax(&g_m[dst], fenc(lg));
}

// ---------------- edge pass B: exp + segment-sum ----------------
__global__ void edge_sum_kernel(const int* __restrict__ ei) {
    int e = blockIdx.x * blockDim.x + threadIdx.x;
    if (e >= E_) return;
    int dst = ei[E_ + e];
    float ex = expf(g_logit[e] - fdec(g_m[dst]));
    atomicAdd(&g_sum[dst], ex);
}

// ---------------- edge pass C: msg + scatter ----------------
__global__ void __launch_bounds__(128)
edge_aggr_kernel(const float* __restrict__ ea, const int* __restrict__ ei,
                 const float* __restrict__ Wlin, float* __restrict__ out) {
    __shared__ float4 sW[64 * 16];
    for (int i = threadIdx.x; i < 64 * 16; i += blockDim.x)
        sW[i] = reinterpret_cast<const float4*>(Wlin + 64 * 64)[i];
    __syncthreads();

    int e = blockIdx.x * blockDim.x + threadIdx.x;
    if (e >= E_) return;

    float4 acc[16];
#pragma unroll
    for (int o4 = 0; o4 < 16; o4++) acc[o4] = make_float4(0.f, 0.f, 0.f, 0.f);

    const float4* in4 = reinterpret_cast<const float4*>(ea) + e * 16;
#pragma unroll 1
    for (int kc = 0; kc < 16; kc++) {
        float4 v4 = in4[kc];
        float vv[4] = {v4.x, v4.y, v4.z, v4.w};
#pragma unroll
        for (int j = 0; j < 4; j++) {
            float v = vv[j];
            const float4* wr = sW + (kc * 4 + j) * 16;
#pragma unroll
            for (int o4 = 0; o4 < 16; o4++) {
                float4 w = wr[o4];
                acc[o4].x += v * w.x; acc[o4].y += v * w.y;
                acc[o4].z += v * w.z; acc[o4].w += v * w.w;
            }
        }
    }

    int src = ei[e];
    int dst = ei[E_ + e];
    float alpha = expf(g_logit[e] - fdec(g_m[dst])) / (g_sum[dst] + 1e-16f);

    const float4* mj4 = reinterpret_cast<const float4*>(g_mj) + src * 16;
    float4* o4p = reinterpret_cast<float4*>(out) + dst * 16;
#pragma unroll
    for (int o4 = 0; o4 < 16; o4++) {
        float4 m4 = mj4[o4];
        float4 val;
        val.x = (m4.x + acc[o4].x) * alpha;
        val.y = (m4.y + acc[o4].y) * alpha;
        val.z = (m4.z + acc[o4].z) * alpha;
        val.w = (m4.w + acc[o4].w) * alpha;
        atomicAdd(o4p + o4, val);   // red.global.add.v4.f32 (sm_90+)
    }
}

// ---------------- final node head ----------------
__global__ void out_node_kernel(const float* __restrict__ h, const int* __restrict__ ntype,
                                const float* __restrict__ Wnc, const float* __restrict__ bnc,
                                float* __restrict__ dout) {
    int n = blockIdx.x * blockDim.x + threadIdx.x;
    if (n >= N_) return;
    int t = ntype[n];
    const float* hr = h + n * 64;
    const float* w = Wnc + t * 64;
    float a = bnc[t];
#pragma unroll
    for (int k = 0; k < 64; k++) a += fmaxf(hr[k], 0.f) * w[k];
    dout[n] = a;
}

// ---------------- launcher ----------------
extern "C" void kernel_launch(void* const* d_in, const int* in_sizes, int n_in,
                              void* d_out, int out_size) {
    const float* x     = (const float*)d_in[0];
    const int*   ei    = (const int*)d_in[1];
    const int*   ntype = (const int*)d_in[2];
    const int*   etype = (const int*)d_in[3];
    const float* eattr = (const float*)d_in[4];

    const float* Whl[3]  = {(const float*)d_in[5],  (const float*)d_in[11], (const float*)d_in[17]};
    const float* bhl[3]  = {(const float*)d_in[6],  (const float*)d_in[12], (const float*)d_in[18]};
    const float* Ete[3]  = {(const float*)d_in[7],  (const float*)d_in[13], (const float*)d_in[19]};
    const float* Wea[3]  = {(const float*)d_in[8],  (const float*)d_in[14], (const float*)d_in[20]};
    const float* Watt[3] = {(const float*)d_in[9],  (const float*)d_in[15], (const float*)d_in[21]};
    const float* Wlin[3] = {(const float*)d_in[10], (const float*)d_in[16], (const float*)d_in[22]};
    const float* Wnc = (const float*)d_in[23];
    const float* bnc = (const float*)d_in[24];
    const float* Wec = (const float*)d_in[25];
    const float* bec = (const float*)d_in[26];

    float *e0, *e1, *outA, *outB;
    cudaGetSymbolAddress((void**)&e0,  g_e0);
    cudaGetSymbolAddress((void**)&e1,  g_e1);
    cudaGetSymbolAddress((void**)&outA, g_outA);
    cudaGetSymbolAddress((void**)&outB, g_outB);

    const int nodeBlocks = (N_ + 127) / 128;
    const int edgeBlocks128 = (E_ + 127) / 128;
    const int edgeBlocks256 = (E_ + 255) / 256;
    const int initBlocks = (N_ * H_ + 255) / 256;

    float* doutN = (float*)d_out;        // node head outputs [0, N)
    float* doutE = (float*)d_out + N_;   // edge head outputs [N, N+E)

    struct Cfg { const float* ein; float* eaout; const float* xin; float* out; };
    Cfg L[3] = {
        { eattr, e0, x,    outA },
        { e0,    e1, outA, outB },
        { e1,    e0, outB, outA },
    };

    for (int l = 0; l < 3; l++) {
        prep_kernel<<<NT_ * 64, 64>>>(Whl[l], bhl[l], Ete[l], Watt[l], Wlin[l]);
        init_kernel<<<initBlocks, 256>>>(L[l].out);
        if (l == 0)
            node_kernel<false><<<nodeBlocks, 128>>>(L[l].xin, ntype);
        else
            node_kernel<true><<<nodeBlocks, 128>>>(L[l].xin, ntype);

        if (l == 0)
            edge_ea_kernel<FE_, false, false><<<edgeBlocks128, 128>>>(
                L[l].ein, ei, etype, Wea[l], Watt[l], L[l].eaout, nullptr, nullptr, nullptr);
        else if (l == 1)
            edge_ea_kernel<H_, true, false><<<edgeBlocks128, 128>>>(
                L[l].ein, ei, etype, Wea[l], Watt[l], L[l].eaout, nullptr, nullptr, nullptr);
        else
            edge_ea_kernel<H_, true, true><<<edgeBlocks128, 128>>>(
                L[l].ein, ei, etype, Wea[l], Watt[l], L[l].eaout, Wec, bec, doutE);

        edge_sum_kernel<<<edgeBlocks256, 256>>>(ei);
        edge_aggr_kernel<<<edgeBlocks128, 128>>>(L[l].eaout, ei, Wlin[l], L[l].out);
    }

    out_node_kernel<<<nodeBlocks, 128>>>(outA, ntype, Wnc, bnc, doutN);
}

// round 3
// speedup vs baseline: 1.5752x; 1.5752x over previous
#include <cuda_runtime.h>
#include <math.h>

#define N_   50000
#define E_   800000
#define HALF_E (E_ / 2)
#define H_   64
#define FE_  32
#define NT_  3
#define ET_  4
#define NEG_ 0.2f

// ---------------- device scratch ----------------
__device__ __align__(16) float g_e0[E_ * H_];
__device__ __align__(16) float g_e1[E_ * H_];
__device__ __align__(16) float g_h [N_ * H_];
__device__ __align__(16) float g_s1[N_ * H_];   // sum alpha * ea
__device__ __align__(16) float g_s2[N_ * H_];   // sum alpha * h[src]
__device__ __align__(16) float g_out[N_ * H_];  // conv output
__device__ float g_sI[N_];
__device__ float g_sJ[N_];
__device__ float g_sum[N_];
__device__ int   g_m[N_];
__device__ float g_logit[E_];

// ---------------- helpers ----------------
__device__ __forceinline__ float lrelu(float x) { return x > 0.f ? x : NEG_ * x; }
__device__ __forceinline__ int   fenc(float f) { int i = __float_as_int(f); return i >= 0 ? i : i ^ 0x7FFFFFFF; }
__device__ __forceinline__ float fdec(int i)   { return __int_as_float(i >= 0 ? i : i ^ 0x7FFFFFFF); }

// ---------------- init: zero accumulators ----------------
__global__ void init_kernel() {
    int i = blockIdx.x * blockDim.x + threadIdx.x;
    if (i < N_ * H_) { g_s1[i] = 0.f; g_s2[i] = 0.f; }
    if (i < N_) { g_m[i] = fenc(-INFINITY); g_sum[i] = 0.f; }
}

// ---------------- node pass: h = act(x)@Whl[t]+bhl[t]; sI=h@Wi; sJ=h@Wj ----
template <bool RELU>
__global__ void __launch_bounds__(128)
node_kernel(const float* __restrict__ xin, const int* __restrict__ ntype,
            const float* __restrict__ Whl, const float* __restrict__ bhl,
            const float* __restrict__ Watt) {
    __shared__ float4 sW[NT_ * H_ * 16];  // 48KB: all 3 type weight matrices
    for (int i = threadIdx.x; i < NT_ * H_ * 16; i += blockDim.x)
        sW[i] = reinterpret_cast<const float4*>(Whl)[i];
    __syncthreads();

    int n = blockIdx.x * blockDim.x + threadIdx.x;
    if (n >= N_) return;
    int t = ntype[n];

    const float4* b4 = reinterpret_cast<const float4*>(bhl) + t * 16;
    float4 acc[16];
#pragma unroll
    for (int o4 = 0; o4 < 16; o4++) acc[o4] = __ldg(b4 + o4);

    const float4* x4 = reinterpret_cast<const float4*>(xin) + n * 16;
    const float4* W4 = sW + t * 1024;
#pragma unroll 1
    for (int kc = 0; kc < 16; kc++) {
        float4 v4 = x4[kc];
        if (RELU) {
            v4.x = fmaxf(v4.x, 0.f); v4.y = fmaxf(v4.y, 0.f);
            v4.z = fmaxf(v4.z, 0.f); v4.w = fmaxf(v4.w, 0.f);
        }
        float vv[4] = {v4.x, v4.y, v4.z, v4.w};
#pragma unroll
        for (int j = 0; j < 4; j++) {
            float v = vv[j];
            const float4* wr = W4 + (kc * 4 + j) * 16;
#pragma unroll
            for (int o4 = 0; o4 < 16; o4++) {
                float4 w = wr[o4];
                acc[o4].x += v * w.x; acc[o4].y += v * w.y;
                acc[o4].z += v * w.z; acc[o4].w += v * w.w;
            }
        }
    }

    float sI = 0.f, sJ = 0.f;
#pragma unroll
    for (int o4 = 0; o4 < 16; o4++) {
        float4 a = acc[o4];
        sI += a.x * __ldg(Watt + o4 * 4)     + a.y * __ldg(Watt + o4 * 4 + 1)
            + a.z * __ldg(Watt + o4 * 4 + 2) + a.w * __ldg(Watt + o4 * 4 + 3);
        sJ += a.x * __ldg(Watt + 64 + o4 * 4)     + a.y * __ldg(Watt + 64 + o4 * 4 + 1)
            + a.z * __ldg(Watt + 64 + o4 * 4 + 2) + a.w * __ldg(Watt + 64 + o4 * 4 + 3);
    }

    float4* h4 = reinterpret_cast<float4*>(g_h) + n * 16;
#pragma unroll
    for (int o4 = 0; o4 < 16; o4++) h4[o4] = acc[o4];
    g_sI[n] = sI;
    g_sJ[n] = sJ;
}

// ---------------- edge pass A epilogue ----------------
__device__ __forceinline__ void ea_epilogue(
    float4 (&acc)[16], int e,
    const int* __restrict__ ei, const int* __restrict__ etype,
    const float* sWe, const float* sEteW,
    float* __restrict__ eaout,
    bool ehead, const float* sWec, const float* sBec, float* __restrict__ eout)
{
    int t = etype[e];
    float pre = 0.f, eo = 0.f;
    const float* wec = sWec + t * 64;
    float4* out4 = reinterpret_cast<float4*>(eaout) + e * 16;
#pragma unroll
    for (int o4 = 0; o4 < 16; o4++) {
        float4 a = acc[o4];
        a.x = lrelu(a.x); a.y = lrelu(a.y); a.z = lrelu(a.z); a.w = lrelu(a.w);
        pre += a.x * sWe[o4 * 4]     + a.y * sWe[o4 * 4 + 1]
             + a.z * sWe[o4 * 4 + 2] + a.w * sWe[o4 * 4 + 3];
        if (ehead) {
            eo += fmaxf(a.x, 0.f) * wec[o4 * 4]     + fmaxf(a.y, 0.f) * wec[o4 * 4 + 1]
                + fmaxf(a.z, 0.f) * wec[o4 * 4 + 2] + fmaxf(a.w, 0.f) * wec[o4 * 4 + 3];
        }
        out4[o4] = a;
    }
    if (ehead) eout[e] = eo + sBec[t];

    int src = ei[e];
    int dst = ei[E_ + e];
    float lg = lrelu(g_sI[dst] + g_sJ[src] + pre + sEteW[t]);
    g_logit[e] = lg;
    atomicMax(&g_m[dst], fenc(lg));
}

// ---------------- edge pass A: ea = lrelu(act(ein)@Wea); logit; seg-max ----
// EPT=2: thread handles edges e and e+HALF_E, amortizing smem weight loads.
template <int IN, bool RELU, bool EHEAD>
__global__ void __launch_bounds__(128)
edge_ea_kernel(const float* __restrict__ ein, const int* __restrict__ ei,
               const int* __restrict__ etype, const float* __restrict__ Wea,
               const float* __restrict__ Watt, const float* __restrict__ Ete,
               float* __restrict__ eaout,
               const float* __restrict__ Wec, const float* __restrict__ bec,
               float* __restrict__ eout) {
    __shared__ float4 sW[IN * 16];
    __shared__ float  sWe[64];
    __shared__ float  sEteW[ET_];
    __shared__ float  sWec[ET_ * 64];
    __shared__ float  sBec[ET_];
    for (int i = threadIdx.x; i < IN * 16; i += blockDim.x)
        sW[i] = reinterpret_cast<const float4*>(Wea)[i];
    if (threadIdx.x < 64) sWe[threadIdx.x] = Watt[132 + threadIdx.x];
    if (threadIdx.x < ET_) {
        float a = 0.f;
#pragma unroll
        for (int j = 0; j < 4; j++) a += lrelu(Ete[threadIdx.x * 4 + j]) * Watt[128 + j];
        sEteW[threadIdx.x] = a;
    }
    if (EHEAD) {
        for (int i = threadIdx.x; i < ET_ * 64; i += blockDim.x) sWec[i] = Wec[i];
        if (threadIdx.x < ET_) sBec[threadIdx.x] = bec[threadIdx.x];
    }
    __syncthreads();

    int e0 = blockIdx.x * blockDim.x + threadIdx.x;   // < HALF_E by grid sizing
    int e1 = e0 + HALF_E;

    float4 acc0[16], acc1[16];
#pragma unroll
    for (int o4 = 0; o4 < 16; o4++) {
        acc0[o4] = make_float4(0.f, 0.f, 0.f, 0.f);
        acc1[o4] = make_float4(0.f, 0.f, 0.f, 0.f);
    }

    const float4* in4 = reinterpret_cast<const float4*>(ein);
    const float4* r0 = in4 + (long)e0 * (IN / 4);
    const float4* r1 = in4 + (long)e1 * (IN / 4);
#pragma unroll 1
    for (int kc = 0; kc < IN / 4; kc++) {
        float4 v0 = r0[kc];
        float4 v1 = r1[kc];
        if (RELU) {
            v0.x = fmaxf(v0.x, 0.f); v0.y = fmaxf(v0.y, 0.f);
            v0.z = fmaxf(v0.z, 0.f); v0.w = fmaxf(v0.w, 0.f);
            v1.x = fmaxf(v1.x, 0.f); v1.y = fmaxf(v1.y, 0.f);
            v1.z = fmaxf(v1.z, 0.f); v1.w = fmaxf(v1.w, 0.f);
        }
        float a0[4] = {v0.x, v0.y, v0.z, v0.w};
        float a1[4] = {v1.x, v1.y, v1.z, v1.w};
#pragma unroll
        for (int j = 0; j < 4; j++) {
            float u0 = a0[j], u1 = a1[j];
            const float4* wr = sW + (kc * 4 + j) * 16;
#pragma unroll
            for (int o4 = 0; o4 < 16; o4++) {
                float4 w = wr[o4];
                acc0[o4].x += u0 * w.x; acc0[o4].y += u0 * w.y;
                acc0[o4].z += u0 * w.z; acc0[o4].w += u0 * w.w;
                acc1[o4].x += u1 * w.x; acc1[o4].y += u1 * w.y;
                acc1[o4].z += u1 * w.z; acc1[o4].w += u1 * w.w;
            }
        }
    }

    ea_epilogue(acc0, e0, ei, etype, sWe, sEteW, eaout, EHEAD, sWec, sBec, eout);
    ea_epilogue(acc1, e1, ei, etype, sWe, sEteW, eaout, EHEAD, sWec, sBec, eout);
}

// ---------------- edge pass B: exp + segment-sum ----------------
__global__ void edge_sum_kernel(const int* __restrict__ ei) {
    int e = blockIdx.x * blockDim.x + threadIdx.x;
    if (e >= E_) return;
    int dst = ei[E_ + e];
    float ex = expf(g_logit[e] - fdec(g_m[dst]));
    atomicAdd(&g_sum[dst], ex);
}

// ---------------- edge pass C: scatter alpha*ea -> s1, alpha*h[src] -> s2 ---
__global__ void __launch_bounds__(256)
edge_scatter_kernel(const float* __restrict__ ea, const int* __restrict__ ei) {
    int gid = blockIdx.x * blockDim.x + threadIdx.x;
    int e = gid >> 3;
    int lane = gid & 7;
    if (e >= E_) return;

    int src = ei[e];
    int dst = ei[E_ + e];
    float alpha = expf(g_logit[e] - fdec(g_m[dst])) / (g_sum[dst] + 1e-16f);

    const float4* ea4 = reinterpret_cast<const float4*>(ea) + (long)e * 16;
    const float4* h4  = reinterpret_cast<const float4*>(g_h) + src * 16;
    float4* s14 = reinterpret_cast<float4*>(g_s1) + dst * 16;
    float4* s24 = reinterpret_cast<float4*>(g_s2) + dst * 16;

#pragma unroll
    for (int c = 0; c < 2; c++) {
        int idx = lane + c * 8;
        float4 a = ea4[idx];
        a.x *= alpha; a.y *= alpha; a.z *= alpha; a.w *= alpha;
        atomicAdd(s14 + idx, a);
        float4 hh = h4[idx];
        hh.x *= alpha; hh.y *= alpha; hh.z *= alpha; hh.w *= alpha;
        atomicAdd(s24 + idx, hh);
    }
}

// ---------------- finish: out = s2 @ Wlin[:H] + s1 @ Wlin[H:] ----------------
__global__ void __launch_bounds__(128)
finish_kernel(const float* __restrict__ Wlin) {
    __shared__ float4 sW[128 * 16];   // 32KB: full (2H x H) Wlin
    for (int i = threadIdx.x; i < 128 * 16; i += blockDim.x)
        sW[i] = reinterpret_cast<const float4*>(Wlin)[i];
    __syncthreads();

    int n = blockIdx.x * blockDim.x + threadIdx.x;
    if (n >= N_) return;

    float4 acc[16];
#pragma unroll
    for (int o4 = 0; o4 < 16; o4++) acc[o4] = make_float4(0.f, 0.f, 0.f, 0.f);

    const float4* r2 = reinterpret_cast<const float4*>(g_s2) + n * 16;  // k 0..63
    const float4* r1 = reinterpret_cast<const float4*>(g_s1) + n * 16;  // k 64..127
#pragma unroll 1
    for (int kc = 0; kc < 16; kc++) {
        float4 v4 = r2[kc];
        float vv[4] = {v4.x, v4.y, v4.z, v4.w};
#pragma unroll
        for (int j = 0; j < 4; j++) {
            float v = vv[j];
            const float4* wr = sW + (kc * 4 + j) * 16;
#pragma unroll
            for (int o4 = 0; o4 < 16; o4++) {
                float4 w = wr[o4];
                acc[o4].x += v * w.x; acc[o4].y += v * w.y;
                acc[o4].z += v * w.z; acc[o4].w += v * w.w;
            }
        }
    }
#pragma unroll 1
    for (int kc = 0; kc < 16; kc++) {
        float4 v4 = r1[kc];
        float vv[4] = {v4.x, v4.y, v4.z, v4.w};
#pragma unroll
        for (int j = 0; j < 4; j++) {
            float v = vv[j];
            const float4* wr = sW + (64 + kc * 4 + j) * 16;
#pragma unroll
            for (int o4 = 0; o4 < 16; o4++) {
                float4 w = wr[o4];
                acc[o4].x += v * w.x; acc[o4].y += v * w.y;
                acc[o4].z += v * w.z; acc[o4].w += v * w.w;
            }
        }
    }

    float4* out4 = reinterpret_cast<float4*>(g_out) + n * 16;
#pragma unroll
    for (int o4 = 0; o4 < 16; o4++) out4[o4] = acc[o4];
}

// ---------------- final node head ----------------
__global__ void out_node_kernel(const int* __restrict__ ntype,
                                const float* __restrict__ Wnc, const float* __restrict__ bnc,
                                float* __restrict__ dout) {
    int n = blockIdx.x * blockDim.x + threadIdx.x;
    if (n >= N_) return;
    int t = ntype[n];
    const float* hr = g_out + n * 64;
    const float* w = Wnc + t * 64;
    float a = bnc[t];
#pragma unroll
    for (int k = 0; k < 64; k++) a += fmaxf(hr[k], 0.f) * __ldg(w + k);
    dout[n] = a;
}

// ---------------- launcher ----------------
extern "C" void kernel_launch(void* const* d_in, const int* in_sizes, int n_in,
                              void* d_out, int out_size) {
    const float* x     = (const float*)d_in[0];
    const int*   ei    = (const int*)d_in[1];
    const int*   ntype = (const int*)d_in[2];
    const int*   etype = (const int*)d_in[3];
    const float* eattr = (const float*)d_in[4];

    const float* Whl[3]  = {(const float*)d_in[5],  (const float*)d_in[11], (const float*)d_in[17]};
    const float* bhl[3]  = {(const float*)d_in[6],  (const float*)d_in[12], (const float*)d_in[18]};
    const float* Ete[3]  = {(const float*)d_in[7],  (const float*)d_in[13], (const float*)d_in[19]};
    const float* Wea[3]  = {(const float*)d_in[8],  (const float*)d_in[14], (const float*)d_in[20]};
    const float* Watt[3] = {(const float*)d_in[9],  (const float*)d_in[15], (const float*)d_in[21]};
    const float* Wlin[3] = {(const float*)d_in[10], (const float*)d_in[16], (const float*)d_in[22]};
    const float* Wnc = (const float*)d_in[23];
    const float* bnc = (const float*)d_in[24];
    const float* Wec = (const float*)d_in[25];
    const float* bec = (const float*)d_in[26];

    float *e0, *e1;
    cudaGetSymbolAddress((void**)&e0, g_e0);
    cudaGetSymbolAddress((void**)&e1, g_e1);

    const int nodeBlocks   = (N_ + 127) / 128;
    const int eaBlocks     = HALF_E / 128;          // 3125
    const int sumBlocks    = (E_ + 255) / 256;      // 3125
    const int scatBlocks   = (E_ * 8) / 256;        // 25000
    const int initBlocks   = (N_ * H_ + 255) / 256;

    float* doutN = (float*)d_out;        // node head [0, N)
    float* doutE = (float*)d_out + N_;   // edge head [N, N+E)

    struct Cfg { const float* ein; float* eaout; const float* xin; };
    Cfg L[3] = {
        { eattr, e0, x },
        { e0,    e1, nullptr },   // xin = g_out (device symbol) for l>=1
        { e1,    e0, nullptr },
    };

    float* outBuf;
    cudaGetSymbolAddress((void**)&outBuf, g_out);
    L[1].xin = outBuf;
    L[2].xin = outBuf;

    for (int l = 0; l < 3; l++) {
        init_kernel<<<initBlocks, 256>>>();
        if (l == 0)
            node_kernel<false><<<nodeBlocks, 128>>>(L[l].xin, ntype, Whl[l], bhl[l], Watt[l]);
        else
            node_kernel<true><<<nodeBlocks, 128>>>(L[l].xin, ntype, Whl[l], bhl[l], Watt[l]);

        if (l == 0)
            edge_ea_kernel<FE_, false, false><<<eaBlocks, 128>>>(
                L[l].ein, ei, etype, Wea[l], Watt[l], Ete[l], L[l].eaout, nullptr, nullptr, nullptr);
        else if (l == 1)
            edge_ea_kernel<H_, true, false><<<eaBlocks, 128>>>(
                L[l].ein, ei, etype, Wea[l], Watt[l], Ete[l], L[l].eaout, nullptr, nullptr, nullptr);
        else
            edge_ea_kernel<H_, true, true><<<eaBlocks, 128>>>(
                L[l].ein, ei, etype, Wea[l], Watt[l], Ete[l], L[l].eaout, Wec, bec, doutE);

        edge_sum_kernel<<<sumBlocks, 256>>>(ei);
        edge_scatter_kernel<<<scatBlocks, 256>>>(L[l].eaout, ei);
        finish_kernel<<<nodeBlocks, 128>>>(Wlin[l]);
    }

    out_node_kernel<<<nodeBlocks, 128>>>(ntype, Wnc, bnc, doutN);
}